// round 13
// baseline (speedup 1.0000x reference)
#include <cuda_runtime.h>
#include <cuda_fp16.h>
#include <math.h>
#include <stdint.h>

#define NB    2
#define NL    1024
#define NV    8
#define NDVP  128
#define NDQ   1024
#define NDSRC 512
#define NW    4
#define NK    8
#define NROWS (NB * NV * NL)

// Scale: wq/wk/bq/bk premultiplied by 64 -> score scaled by 4096 (top-k safe)
#define WSCALE 64.0f
#define INV_SCORE_SCALE (1.0f / 4096.0f)

// ---------------------------------------------------------------------------
// Scratch: packed fp16 hi/lo operands, word = half2 (k_even, k_odd),
// layout word[k/2][m] (k-pair-major).
// ---------------------------------------------------------------------------
__device__ uint32_t g_qh [512 * 2048], g_ql [512 * 2048];  // query   [k2][b*l]
__device__ uint32_t g_kh [512 * 2048], g_kl [512 * 2048];  // key_t   [k2][b*l]
__device__ uint32_t g_wqh[512 * 1024], g_wql[512 * 1024];  // 64*wq   [k2][v*dvp]
__device__ uint32_t g_wkh[512 * 1024], g_wkl[512 * 1024];  // 64*wk   [k2][v*dvp]
__device__ uint32_t g_pqh[512 * 2048], g_pql[512 * 2048];  // q'      [v*64+d2][b*l]
__device__ uint32_t g_pkh[512 * 2048], g_pkl[512 * 2048];  // k'      [v*64+d2][b*l]
__device__ float    g_score[16 * 1024 * 1024];             // 4096*score
__device__ float    g_wt[NROWS * NK];
__device__ int      g_ix[NROWS * NK];

// ---------------------------------------------------------------------------
// helpers
// ---------------------------------------------------------------------------
__device__ __forceinline__ uint32_t smem_u32(const void* p) {
    uint32_t a;
    asm("{ .reg .u64 t; cvta.to.shared.u64 t, %1; cvt.u32.u64 %0, t; }" : "=r"(a) : "l"(p));
    return a;
}
__device__ __forceinline__ void cp16(uint32_t dst, const void* src) {
    asm volatile("cp.async.cg.shared.global [%0], [%1], 16;" :: "r"(dst), "l"(src) : "memory");
}
__device__ __forceinline__ void cp_commit() { asm volatile("cp.async.commit_group;" ::: "memory"); }
__device__ __forceinline__ void cp_wait1()  { asm volatile("cp.async.wait_group 1;" ::: "memory"); }
__device__ __forceinline__ void cp_wait0()  { asm volatile("cp.async.wait_group 0;" ::: "memory"); }

__device__ __forceinline__ void mma_f16(float* d, const uint32_t* a, const uint32_t* b) {
    asm volatile(
        "mma.sync.aligned.m16n8k16.row.col.f32.f16.f16.f32 "
        "{%0,%1,%2,%3}, {%4,%5,%6,%7}, {%8,%9}, {%0,%1,%2,%3};"
        : "+f"(d[0]), "+f"(d[1]), "+f"(d[2]), "+f"(d[3])
        : "r"(a[0]), "r"(a[1]), "r"(a[2]), "r"(a[3]), "r"(b[0]), "r"(b[1]));
}

__device__ __forceinline__ uint32_t pack2h(__half a, __half b) {
    __half2 t = __halves2half2(a, b);
    return *reinterpret_cast<uint32_t*>(&t);
}
// fp16 hi/lo split of two consecutive-k values -> packed hi word + lo word
__device__ __forceinline__ void fp16_split2(float v0, float v1, uint32_t& hw, uint32_t& lw) {
    const __half h0 = __float2half_rn(v0), h1 = __float2half_rn(v1);
    const float  l0 = v0 - __half2float(h0), l1 = v1 - __half2float(h1);
    hw = pack2h(h0, h1);
    lw = pack2h(__float2half_rn(l0), __float2half_rn(l1));
}

// ---------------------------------------------------------------------------
// GEMM: BM=128, BN=128, BK=32 (16 k2 word-rows), 256 threads (8 warps 4x2),
// warp tile 32x64, 3-buffer single-barrier cp.async pipeline. 2 CTAs/SM.
// Smem tiles [16][136] words (stride 136 -> conflict-free, proven R5/R8).
// ---------------------------------------------------------------------------
#define SA        136
#define TILE_W    (16 * SA)          // 2176 words per tile
#define OFF_AH    0
#define OFF_AL    (1 * TILE_W)
#define OFF_BH    (2 * TILE_W)
#define OFF_BL    (3 * TILE_W)
#define STAGE_W   (4 * TILE_W)       // 8704 words
#define NSTAGE    3
#define SMEM_BYTES (NSTAGE * STAGE_W * 4)  // 104448 bytes

__device__ __forceinline__ void load_tile(uint32_t sb, const uint32_t* src, int ld) {
    #pragma unroll
    for (int i = 0; i < 2; i++) {
        const int id = threadIdx.x + i * 256;       // 512 16B chunks (16 rows x 32)
        const int k = id >> 5, mc = id & 31;
        cp16(sb + (uint32_t)(k * SA + mc * 4) * 4, src + (size_t)k * ld + mc * 4);
    }
}

__device__ __forceinline__ void load_stage(uint32_t sb,
    const uint32_t* Ah, const uint32_t* Al, int lda,
    const uint32_t* Bh, const uint32_t* Bl, int ldb, int r0)   // r0 = k2 row
{
    load_tile(sb + OFF_AH * 4, Ah + (size_t)r0 * lda, lda);
    load_tile(sb + OFF_AL * 4, Al + (size_t)r0 * lda, lda);
    load_tile(sb + OFF_BH * 4, Bh + (size_t)r0 * ldb, ldb);
    load_tile(sb + OFF_BL * 4, Bl + (size_t)r0 * ldb, ldb);
    cp_commit();
}

// Product-major MMA issue order: within each nbh block, issue HHx8, HLx8,
// LHx8 so 8 independent accumulators sit between successive touches of the
// same d register (covers HMMA RAW latency; tensor pipe stays fed).
__device__ __forceinline__ void compute_stage(const uint32_t* s, int warp_m, int warp_n,
                                              float acc[2][8][4])
{
    const int lane = threadIdx.x & 31;
    const int g = lane >> 2, tg = lane & 3;
    #pragma unroll
    for (int h = 0; h < 2; h++) {                    // two k16 halves per k32 stage
        const int r0 = (h * 8 + tg) * SA, r1 = (h * 8 + tg + 4) * SA;
        uint32_t aH[2][4], aL[2][4];
        #pragma unroll
        for (int ma = 0; ma < 2; ma++) {
            const int m = warp_m + ma * 16 + g;
            aH[ma][0] = s[OFF_AH + r0 + m];
            aH[ma][1] = s[OFF_AH + r0 + m + 8];
            aH[ma][2] = s[OFF_AH + r1 + m];
            aH[ma][3] = s[OFF_AH + r1 + m + 8];
            aL[ma][0] = s[OFF_AL + r0 + m];
            aL[ma][1] = s[OFF_AL + r0 + m + 8];
            aL[ma][2] = s[OFF_AL + r1 + m];
            aL[ma][3] = s[OFF_AL + r1 + m + 8];
        }
        #pragma unroll
        for (int nbh = 0; nbh < 2; nbh++) {
            uint32_t bH[4][2], bL[4][2];
            #pragma unroll
            for (int j = 0; j < 4; j++) {
                const int n = warp_n + (nbh * 4 + j) * 8 + g;
                bH[j][0] = s[OFF_BH + r0 + n];
                bH[j][1] = s[OFF_BH + r1 + n];
                bL[j][0] = s[OFF_BL + r0 + n];
                bL[j][1] = s[OFF_BL + r1 + n];
            }
            // HH sweep (8 independent d)
            #pragma unroll
            for (int ma = 0; ma < 2; ma++)
                #pragma unroll
                for (int j = 0; j < 4; j++)
                    mma_f16(acc[ma][nbh * 4 + j], aH[ma], bH[j]);
            // HL sweep
            #pragma unroll
            for (int ma = 0; ma < 2; ma++)
                #pragma unroll
                for (int j = 0; j < 4; j++)
                    mma_f16(acc[ma][nbh * 4 + j], aH[ma], bL[j]);
            // LH sweep
            #pragma unroll
            for (int ma = 0; ma < 2; ma++)
                #pragma unroll
                for (int j = 0; j < 4; j++)
                    mma_f16(acc[ma][nbh * 4 + j], aL[ma], bH[j]);
        }
    }
}

__device__ __forceinline__ void gemm_mainloop(
    const uint32_t* Ah, const uint32_t* Al, int lda,
    const uint32_t* Bh, const uint32_t* Bl, int ldb,
    int nstages, float acc[2][8][4], uint32_t* smem)
{
    const uint32_t sb = smem_u32(smem);
    const int warp = threadIdx.x >> 5;
    const int warp_m = (warp & 3) * 32, warp_n = (warp >> 2) * 64;

    load_stage(sb,               Ah, Al, lda, Bh, Bl, ldb, 0);
    load_stage(sb + STAGE_W * 4, Ah, Al, lda, Bh, Bl, ldb, 16);

    for (int t = 0; t < nstages; ++t) {
        if (t == nstages - 1) cp_wait0(); else cp_wait1();
        __syncthreads();
        if (t + 2 < nstages)
            load_stage(sb + (uint32_t)((t + 2) % NSTAGE) * STAGE_W * 4,
                       Ah, Al, lda, Bh, Bl, ldb, (t + 2) * 16);
        compute_stage(smem + (t % NSTAGE) * STAGE_W, warp_m, warp_n, acc);
    }
}

// ---------------------------------------------------------------------------
// Kernel 1a: split+transpose query & key -> packed fp16 hi/lo [k2][m].
// grid (32, 64, 2), block (32, 8).
// ---------------------------------------------------------------------------
__global__ void __launch_bounds__(256) split_qk_kernel(
    const float* __restrict__ Q, const float* __restrict__ K)
{
    __shared__ float sh[32][33];
    const float* X = blockIdx.z ? K : Q;
    uint32_t* Hi = blockIdx.z ? g_kh : g_qh;
    uint32_t* Lo = blockIdx.z ? g_kl : g_ql;
    const int tx = threadIdx.x, ty = threadIdx.y;
    const int c0 = blockIdx.x * 32, r0 = blockIdx.y * 32;   // c: k, r: m
    #pragma unroll
    for (int j = 0; j < 4; j++)
        sh[ty + j * 8][tx] = X[(size_t)(r0 + ty + j * 8) * 1024 + c0 + tx];
    __syncthreads();
    #pragma unroll
    for (int j = 0; j < 2; j++) {
        const int k2l = ty + j * 8;                          // 0..15
        uint32_t hw, lw;
        fp16_split2(sh[tx][2 * k2l], sh[tx][2 * k2l + 1], hw, lw);
        const size_t o = (size_t)((c0 >> 1) + k2l) * 2048 + r0 + tx;
        Hi[o] = hw; Lo[o] = lw;
    }
}

// ---------------------------------------------------------------------------
// Kernel 1b: split+transpose 64*wq & 64*wk -> packed fp16 hi/lo [k2][n].
// grid (32, 32, 2), block (32, 8).
// ---------------------------------------------------------------------------
__global__ void __launch_bounds__(256) split_w_kernel(
    const float* __restrict__ WQ, const float* __restrict__ WK)
{
    __shared__ float sh[32][33];
    const float* X = blockIdx.z ? WK : WQ;
    uint32_t* Hi = blockIdx.z ? g_wkh : g_wqh;
    uint32_t* Lo = blockIdx.z ? g_wkl : g_wql;
    const int tx = threadIdx.x, ty = threadIdx.y;
    const int c0 = blockIdx.x * 32, r0 = blockIdx.y * 32;   // c: k, r: n
    #pragma unroll
    for (int j = 0; j < 4; j++)
        sh[ty + j * 8][tx] = WSCALE * X[(size_t)(r0 + ty + j * 8) * 1024 + c0 + tx];
    __syncthreads();
    #pragma unroll
    for (int j = 0; j < 2; j++) {
        const int k2l = ty + j * 8;
        uint32_t hw, lw;
        fp16_split2(sh[tx][2 * k2l], sh[tx][2 * k2l + 1], hw, lw);
        const size_t o = (size_t)((c0 >> 1) + k2l) * 1024 + r0 + tx;
        Hi[o] = hw; Lo[o] = lw;
    }
}

// ---------------------------------------------------------------------------
// Kernel 2: projections. z=0 -> q', z=1 -> k'. grid (8, 16, 2), 256 thr.
// Epilogue: stage fp32 tile transposed in smem, then packed fp16 hi/lo
// stores (pairs of consecutive dvp dims) -> [d2][m] layout, coalesced.
// ---------------------------------------------------------------------------
#define EP_ST 132

__global__ void __launch_bounds__(256, 2) proj_mma_kernel(
    const float* __restrict__ bq, const float* __restrict__ bk)
{
    extern __shared__ uint32_t smem[];
    float* smf = (float*)smem;
    const int z = blockIdx.z;
    const int m0 = blockIdx.y * 128, n0 = blockIdx.x * 128;

    const uint32_t* Ah = (z ? g_kh : g_qh) + m0;      // [512][2048]
    const uint32_t* Al = (z ? g_kl : g_ql) + m0;
    const uint32_t* Bh = (z ? g_wkh : g_wqh) + n0;    // [512][1024]
    const uint32_t* Bl = (z ? g_wkl : g_wql) + n0;

    float acc[2][8][4];
    #pragma unroll
    for (int i = 0; i < 2; i++)
        #pragma unroll
        for (int j = 0; j < 8; j++)
            #pragma unroll
            for (int r = 0; r < 4; r++) acc[i][j][r] = 0.f;

    gemm_mainloop(Ah, Al, 2048, Bh, Bl, 1024, NDQ / 32, acc, smem);

    const int warp = threadIdx.x >> 5, lane = threadIdx.x & 31;
    const int warp_m = (warp & 3) * 32, warp_n = (warp >> 2) * 64;
    const int g = lane >> 2, tg = lane & 3;

    __syncthreads();   // smem reuse safe
    #pragma unroll
    for (int ma = 0; ma < 2; ma++)
        #pragma unroll
        for (int nb = 0; nb < 8; nb++) {
            const int row = warp_m + ma * 16 + g;
            const int col = warp_n + nb * 8 + 2 * tg;
            #pragma unroll
            for (int rr = 0; rr < 4; rr++)
                smf[(col + (rr & 1)) * EP_ST + row + (rr >> 1) * 8] = acc[ma][nb][rr];
        }
    __syncthreads();

    const float* bias = z ? bk : bq;
    uint32_t* Ho = z ? g_pkh : g_pqh;
    uint32_t* Lo = z ? g_pkl : g_pql;

    // 64 col-pairs; warp w handles pairs w, w+8, ... ; lane covers 4 m values
    #pragma unroll
    for (int i = 0; i < 8; i++) {
        const int c2l = i * 8 + warp;
        const float bA = WSCALE * __ldg(&bias[n0 + 2 * c2l]);
        const float bB = WSCALE * __ldg(&bias[n0 + 2 * c2l + 1]);
        const float4 va = *(const float4*)&smf[(2 * c2l) * EP_ST + 4 * lane];
        const float4 vb = *(const float4*)&smf[(2 * c2l + 1) * EP_ST + 4 * lane];
        uint32_t hw[4], lw[4];
        fp16_split2(va.x + bA, vb.x + bB, hw[0], lw[0]);
        fp16_split2(va.y + bA, vb.y + bB, hw[1], lw[1]);
        fp16_split2(va.z + bA, vb.z + bB, hw[2], lw[2]);
        fp16_split2(va.w + bA, vb.w + bB, hw[3], lw[3]);
        const size_t o = (size_t)((n0 >> 1) + c2l) * 2048 + m0 + 4 * lane;
        *(uint4*)&Ho[o] = make_uint4(hw[0], hw[1], hw[2], hw[3]);
        *(uint4*)&Lo[o] = make_uint4(lw[0], lw[1], lw[2], lw[3]);
    }
}

// ---------------------------------------------------------------------------
// Kernel 3: score'[b,v] = q'_v * k'_v^T (K=128, 4096x scaled). grid (8,8,16).
// ---------------------------------------------------------------------------
__global__ void __launch_bounds__(256, 2) score_mma_kernel()
{
    extern __shared__ uint32_t smem[];
    const int z = blockIdx.z;
    const int b = z >> 3, v = z & 7;
    const int m0 = blockIdx.y * 128, n0 = blockIdx.x * 128;

    const size_t base = (size_t)(v * 64) * 2048 + b * 1024;
    const uint32_t* Ah = g_pqh + base + m0;
    const uint32_t* Al = g_pql + base + m0;
    const uint32_t* Bh = g_pkh + base + n0;
    const uint32_t* Bl = g_pkl + base + n0;

    float acc[2][8][4];
    #pragma unroll
    for (int i = 0; i < 2; i++)
        #pragma unroll
        for (int j = 0; j < 8; j++)
            #pragma unroll
            for (int r = 0; r < 4; r++) acc[i][j][r] = 0.f;

    gemm_mainloop(Ah, Al, 2048, Bh, Bl, 2048, NDVP / 32, acc, smem);

    float* C = g_score + ((size_t)z << 20);
    const int warp = threadIdx.x >> 5, lane = threadIdx.x & 31;
    const int warp_m = (warp & 3) * 32, warp_n = (warp >> 2) * 64;
    const int g = lane >> 2, tg = lane & 3;

    #pragma unroll
    for (int ma = 0; ma < 2; ma++)
        #pragma unroll
        for (int nb = 0; nb < 8; nb++) {
            const int row = m0 + warp_m + ma * 16 + g;
            const int col = n0 + warp_n + nb * 8 + 2 * tg;
            *(float2*)&C[(size_t)row * 1024 + col] =
                make_float2(acc[ma][nb][0], acc[ma][nb][1]);
            *(float2*)&C[(size_t)(row + 8) * 1024 + col] =
                make_float2(acc[ma][nb][2], acc[ma][nb][3]);
        }
}

// ---------------------------------------------------------------------------
// Kernel 4: top-8 + softmax per score row (scores are 4096x; softmax rescales).
// ---------------------------------------------------------------------------
__global__ void __launch_bounds__(256) topk_kernel()
{
    const int rid  = blockIdx.x * 8 + (threadIdx.x >> 5);
    const int lane = threadIdx.x & 31;
    const float* row = g_score + (size_t)rid * NL;

    float best[NK];
    int   bidx[NK];
    #pragma unroll
    for (int j = 0; j < NK; j++) { best[j] = -INFINITY; bidx[j] = 0x7fffffff; }

    #pragma unroll 4
    for (int i = 0; i < 32; i++) {
        const int idx = i * 32 + lane;
        const float val = row[idx];
        if (val > best[NK - 1]) {
            best[NK - 1] = val; bidx[NK - 1] = idx;
            #pragma unroll
            for (int j = NK - 1; j > 0; --j) {
                if (best[j] > best[j - 1]) {
                    float tv = best[j]; best[j] = best[j - 1]; best[j - 1] = tv;
                    int   ti = bidx[j]; bidx[j] = bidx[j - 1]; bidx[j - 1] = ti;
                }
            }
        }
    }

    float vals[NK]; int inds[NK];
    #pragma unroll
    for (int r = 0; r < NK; r++) {
        float v0 = best[0]; int i0 = bidx[0];
        #pragma unroll
        for (int off = 16; off > 0; off >>= 1) {
            float ov = __shfl_down_sync(0xffffffffu, v0, off);
            int   oi = __shfl_down_sync(0xffffffffu, i0, off);
            if (ov > v0 || (ov == v0 && oi < i0)) { v0 = ov; i0 = oi; }
        }
        v0 = __shfl_sync(0xffffffffu, v0, 0);
        i0 = __shfl_sync(0xffffffffu, i0, 0);
        vals[r] = v0; inds[r] = i0;
        if (lane == (i0 & 31)) {
            #pragma unroll
            for (int j = 0; j < NK - 1; j++) { best[j] = best[j + 1]; bidx[j] = bidx[j + 1]; }
            best[NK - 1] = -INFINITY; bidx[NK - 1] = 0x7fffffff;
        }
    }

    if (lane == 0) {
        const float m = vals[0];
        float e[NK], sum = 0.f;
        #pragma unroll
        for (int r = 0; r < NK; r++) {
            e[r] = expf((vals[r] - m) * INV_SCORE_SCALE);
            sum += e[r];
        }
        const float inv = 1.f / sum;
        #pragma unroll
        for (int r = 0; r < NK; r++) {
            g_wt[rid * NK + r] = e[r] * inv;
            g_ix[rid * NK + r] = inds[r];
        }
    }
}

// ---------------------------------------------------------------------------
// Kernel 5: windowed gather + weighted sum. grid (1024, 8, 2), 256 threads.
// ---------------------------------------------------------------------------
__global__ void __launch_bounds__(256) out_kernel(
    const float* __restrict__ source, float* __restrict__ out)
{
    const int q = blockIdx.x, v = blockIdx.y, b = blockIdx.z;
    const int tid = threadIdx.x;
    const int rid = (b * NV + v) * NL + q;

    float wloc[NK]; int iloc[NK];
    #pragma unroll
    for (int r = 0; r < NK; r++) {
        wloc[r] = __ldg(&g_wt[rid * NK + r]);
        iloc[r] = __ldg(&g_ix[rid * NK + r]);
    }

    const float4* src4 = (const float4*)(source + b * (NL * NDSRC));
    float4* out4 = (float4*)out + (size_t)rid * (NW * NDSRC / 4);

    #pragma unroll
    for (int e2 = 0; e2 < 2; e2++) {
        const int id = tid + e2 * 256;
        const int w = id >> 7;
        const int f = id & 127;
        float4 acc = make_float4(0.f, 0.f, 0.f, 0.f);
        #pragma unroll
        for (int r = 0; r < NK; r++) {
            const int rr = iloc[r] + w - 1;
            if ((unsigned)rr < (unsigned)NL) {
                const float4 s = __ldg(&src4[rr * (NDSRC / 4) + f]);
                const float wt = wloc[r];
                acc.x += wt * s.x; acc.y += wt * s.y;
                acc.z += wt * s.z; acc.w += wt * s.w;
            }
        }
        out4[id] = acc;
    }
}

// ---------------------------------------------------------------------------
extern "C" void kernel_launch(void* const* d_in, const int* in_sizes, int n_in,
                              void* d_out, int out_size)
{
    const float* query  = (const float*)d_in[0];
    const float* key_t  = (const float*)d_in[1];
    const float* source = (const float*)d_in[2];
    const float* wq     = (const float*)d_in[3];
    const float* bq     = (const float*)d_in[4];
    const float* wk     = (const float*)d_in[5];
    const float* bk     = (const float*)d_in[6];
    float* out = (float*)d_out;

    static int inited = 0;
    if (!inited) {
        cudaFuncSetAttribute(proj_mma_kernel,  cudaFuncAttributeMaxDynamicSharedMemorySize, SMEM_BYTES);
        cudaFuncSetAttribute(score_mma_kernel, cudaFuncAttributeMaxDynamicSharedMemorySize, SMEM_BYTES);
        inited = 1;
    }

    // 1) split inputs into packed fp16 hi/lo (weights/bias scaled by 64)
    split_qk_kernel<<<dim3(32, 64, 2), dim3(32, 8)>>>(query, key_t);
    split_w_kernel<<<dim3(32, 32, 2), dim3(32, 8)>>>(wq, wk);

    // 2) projections (fp16x3 tensor path)
    proj_mma_kernel<<<dim3(8, 16, 2), 256, SMEM_BYTES>>>(bq, bk);

    // 3) score GEMMs (fp16x3)
    score_mma_kernel<<<dim3(8, 8, 16), 256, SMEM_BYTES>>>();

    // 4) top-8 + softmax (rescale by 1/4096)
    topk_kernel<<<NROWS / 8, 256>>>();

    // 5) gather + weighted sum
    out_kernel<<<dim3(NL, NV, NB), 256>>>(source, out);
}

// round 15
// speedup vs baseline: 1.0341x; 1.0341x over previous
#include <cuda_runtime.h>
#include <cuda_fp16.h>
#include <math.h>
#include <stdint.h>

#define NB    2
#define NL    1024
#define NV    8
#define NDVP  128
#define NDQ   1024
#define NDSRC 512
#define NW    4
#define NK    8
#define NROWS (NB * NV * NL)

// Scale: wq/wk/bq/bk premultiplied by 64 -> score scaled by 4096 (top-k safe)
#define WSCALE 64.0f
#define INV_SCORE_SCALE (1.0f / 4096.0f)

// ---------------------------------------------------------------------------
// Scratch: packed fp16 hi/lo operands, word = half2 (k_even, k_odd),
// ROW-MAJOR [row][k/2] (k fastest) -> ldmatrix-compatible.
// ---------------------------------------------------------------------------
__device__ uint32_t g_qh [2048 * 512], g_ql [2048 * 512];  // query   [b*l][k2]
__device__ uint32_t g_kh [2048 * 512], g_kl [2048 * 512];  // key_t   [b*l][k2]
__device__ uint32_t g_wqh[1024 * 512], g_wql[1024 * 512];  // 64*wq   [n][k2]
__device__ uint32_t g_wkh[1024 * 512], g_wkl[1024 * 512];  // 64*wk   [n][k2]
__device__ uint32_t g_pqh[2048 * 512], g_pql[2048 * 512];  // q'      [b*l][(v*128+d)/2]
__device__ uint32_t g_pkh[2048 * 512], g_pkl[2048 * 512];  // k'      [b*l][(v*128+d)/2]
__device__ float    g_score[16 * 1024 * 1024];             // 4096*score
__device__ float    g_wt[NROWS * NK];
__device__ int      g_ix[NROWS * NK];

// ---------------------------------------------------------------------------
// helpers
// ---------------------------------------------------------------------------
__device__ __forceinline__ uint32_t smem_u32(const void* p) {
    uint32_t a;
    asm("{ .reg .u64 t; cvta.to.shared.u64 t, %1; cvt.u32.u64 %0, t; }" : "=r"(a) : "l"(p));
    return a;
}
__device__ __forceinline__ void cp16(uint32_t dst, const void* src) {
    asm volatile("cp.async.cg.shared.global [%0], [%1], 16;" :: "r"(dst), "l"(src) : "memory");
}
__device__ __forceinline__ void cp_commit() { asm volatile("cp.async.commit_group;" ::: "memory"); }
__device__ __forceinline__ void cp_wait1()  { asm volatile("cp.async.wait_group 1;" ::: "memory"); }
__device__ __forceinline__ void cp_wait0()  { asm volatile("cp.async.wait_group 0;" ::: "memory"); }

__device__ __forceinline__ void mma_f16(float* d, const uint32_t* a, const uint32_t* b) {
    asm volatile(
        "mma.sync.aligned.m16n8k16.row.col.f32.f16.f16.f32 "
        "{%0,%1,%2,%3}, {%4,%5,%6,%7}, {%8,%9}, {%0,%1,%2,%3};"
        : "+f"(d[0]), "+f"(d[1]), "+f"(d[2]), "+f"(d[3])
        : "r"(a[0]), "r"(a[1]), "r"(a[2]), "r"(a[3]), "r"(b[0]), "r"(b[1]));
}

__device__ __forceinline__ void ldsm4(uint32_t& r0, uint32_t& r1, uint32_t& r2, uint32_t& r3,
                                      uint32_t addr) {
    asm volatile("ldmatrix.sync.aligned.m8n8.x4.shared.b16 {%0,%1,%2,%3}, [%4];"
                 : "=r"(r0), "=r"(r1), "=r"(r2), "=r"(r3) : "r"(addr));
}

__device__ __forceinline__ uint32_t pack2h(__half a, __half b) {
    __half2 t = __halves2half2(a, b);
    return *reinterpret_cast<uint32_t*>(&t);
}
__device__ __forceinline__ void fp16_split2(float v0, float v1, uint32_t& hw, uint32_t& lw) {
    const __half h0 = __float2half_rn(v0), h1 = __float2half_rn(v1);
    const float  l0 = v0 - __half2float(h0), l1 = v1 - __half2float(h1);
    hw = pack2h(h0, h1);
    lw = pack2h(__float2half_rn(l0), __float2half_rn(l1));
}

// ---------------------------------------------------------------------------
// GEMM: BM=128, BN=128, BK=32 halves (16 words), 256 threads (8 warps 4x2),
// warp tile 32x64, 3-buffer single-barrier cp.async pipeline, ldmatrix loads.
// Smem tile: 128 rows x 16 words (64B rows), XOR chunk swizzle c^((r>>1)&3)
// -> ldmatrix conflict-free (8 rows of a matrix cover all 8 granules).
// ---------------------------------------------------------------------------
#define TILE_W    2048               // 128 x 16 words
#define OFF_AH    0
#define OFF_AL    (1 * TILE_W)
#define OFF_BH    (2 * TILE_W)
#define OFF_BL    (3 * TILE_W)
#define STAGE_W   (4 * TILE_W)       // 8192 words
#define NSTAGE    3
#define SMEM_BYTES (NSTAGE * STAGE_W * 4)  // 98304 bytes

// smem word offset of 16B chunk (r, c)
__device__ __forceinline__ uint32_t swoff(int r, int c) {
    return (uint32_t)((r << 4) + ((c ^ ((r >> 1) & 3)) << 2));
}

__device__ __forceinline__ void load_tile(uint32_t sb, const uint32_t* src, int ld) {
    #pragma unroll
    for (int i = 0; i < 2; i++) {
        const int id = threadIdx.x + i * 256;   // 512 chunks: 128 rows x 4
        const int r = id >> 2, c = id & 3;
        cp16(sb + swoff(r, c) * 4, src + (size_t)r * ld + 4 * c);
    }
}

__device__ __forceinline__ void load_stage(uint32_t sb,
    const uint32_t* Ah, const uint32_t* Al, int lda,
    const uint32_t* Bh, const uint32_t* Bl, int ldb, int k0)   // k0 in words
{
    load_tile(sb + OFF_AH * 4, Ah + k0, lda);
    load_tile(sb + OFF_AL * 4, Al + k0, lda);
    load_tile(sb + OFF_BH * 4, Bh + k0, ldb);
    load_tile(sb + OFF_BL * 4, Bl + k0, ldb);
    cp_commit();
}

__device__ __forceinline__ void compute_stage(uint32_t sb, int warp_m, int warp_n,
                                              float acc[2][8][4])
{
    const int lane = threadIdx.x & 31;
    // A fragment lane geometry for m16n8k16 row-major A
    const int arow = (lane & 7) + ((lane >> 3) & 1) * 8;
    const int acs  = lane >> 4;
    // B fragment lane geometry for col-major B (two 8-row n-tiles per ldsm4)
    const int brow = (lane & 7) + (lane >> 4) * 8;
    const int bcs  = (lane >> 3) & 1;

    #pragma unroll
    for (int h = 0; h < 2; h++) {
        uint32_t aH[2][4], aL[2][4];
        #pragma unroll
        for (int ma = 0; ma < 2; ma++) {
            const int r = warp_m + ma * 16 + arow;
            const int c = 2 * h + acs;
            const uint32_t off = swoff(r, c) * 4;
            ldsm4(aH[ma][0], aH[ma][1], aH[ma][2], aH[ma][3], sb + OFF_AH * 4 + off);
            ldsm4(aL[ma][0], aL[ma][1], aL[ma][2], aL[ma][3], sb + OFF_AL * 4 + off);
        }
        #pragma unroll
        for (int nbh = 0; nbh < 2; nbh++) {
            uint32_t bH[4][2], bL[4][2];
            #pragma unroll
            for (int jp = 0; jp < 2; jp++) {
                const int r = warp_n + (nbh * 4 + jp * 2) * 8 + brow;
                const int c = 2 * h + bcs;
                const uint32_t off = swoff(r, c) * 4;
                ldsm4(bH[2*jp][0], bH[2*jp][1], bH[2*jp+1][0], bH[2*jp+1][1],
                      sb + OFF_BH * 4 + off);
                ldsm4(bL[2*jp][0], bL[2*jp][1], bL[2*jp+1][0], bL[2*jp+1][1],
                      sb + OFF_BL * 4 + off);
            }
            #pragma unroll
            for (int ma = 0; ma < 2; ma++)
                #pragma unroll
                for (int j = 0; j < 4; j++)
                    mma_f16(acc[ma][nbh * 4 + j], aH[ma], bH[j]);
            #pragma unroll
            for (int ma = 0; ma < 2; ma++)
                #pragma unroll
                for (int j = 0; j < 4; j++)
                    mma_f16(acc[ma][nbh * 4 + j], aH[ma], bL[j]);
            #pragma unroll
            for (int ma = 0; ma < 2; ma++)
                #pragma unroll
                for (int j = 0; j < 4; j++)
                    mma_f16(acc[ma][nbh * 4 + j], aL[ma], bH[j]);
        }
    }
}

__device__ __forceinline__ void gemm_mainloop(
    const uint32_t* Ah, const uint32_t* Al, int lda,
    const uint32_t* Bh, const uint32_t* Bl, int ldb,
    int nstages, float acc[2][8][4], uint32_t* smem)
{
    const uint32_t sb = smem_u32(smem);
    const int warp = threadIdx.x >> 5;
    const int warp_m = (warp & 3) * 32, warp_n = (warp >> 2) * 64;

    load_stage(sb,               Ah, Al, lda, Bh, Bl, ldb, 0);
    load_stage(sb + STAGE_W * 4, Ah, Al, lda, Bh, Bl, ldb, 16);

    for (int t = 0; t < nstages; ++t) {
        if (t == nstages - 1) cp_wait0(); else cp_wait1();
        __syncthreads();
        if (t + 2 < nstages)
            load_stage(sb + (uint32_t)((t + 2) % NSTAGE) * STAGE_W * 4,
                       Ah, Al, lda, Bh, Bl, ldb, (t + 2) * 16);
        compute_stage(sb + (uint32_t)(t % NSTAGE) * STAGE_W * 4, warp_m, warp_n, acc);
    }
}

// ---------------------------------------------------------------------------
// Kernel 1a: split query & key -> packed fp16 hi/lo [m][k2] (NO transpose).
// grid (4096, 1, 2), 256 thr. Flat copy: word id <-> float pair id.
// ---------------------------------------------------------------------------
__global__ void __launch_bounds__(256) split_qk_kernel(
    const float* __restrict__ Q, const float* __restrict__ K)
{
    const float2* X = (const float2*)(blockIdx.z ? K : Q);
    uint32_t* Hi = blockIdx.z ? g_kh : g_qh;
    uint32_t* Lo = blockIdx.z ? g_kl : g_ql;
    const int id = blockIdx.x * 256 + threadIdx.x;
    const float2 v = X[id];
    uint32_t hw, lw;
    fp16_split2(v.x, v.y, hw, lw);
    Hi[id] = hw; Lo[id] = lw;
}

// ---------------------------------------------------------------------------
// Kernel 1b: split 64*wq & 64*wk -> packed fp16 hi/lo [n][k2].
// grid (2048, 1, 2), 256 thr.
// ---------------------------------------------------------------------------
__global__ void __launch_bounds__(256) split_w_kernel(
    const float* __restrict__ WQ, const float* __restrict__ WK)
{
    const float2* X = (const float2*)(blockIdx.z ? WK : WQ);
    uint32_t* Hi = blockIdx.z ? g_wkh : g_wqh;
    uint32_t* Lo = blockIdx.z ? g_wkl : g_wql;
    const int id = blockIdx.x * 256 + threadIdx.x;
    const float2 v = X[id];
    uint32_t hw, lw;
    fp16_split2(WSCALE * v.x, WSCALE * v.y, hw, lw);
    Hi[id] = hw; Lo[id] = lw;
}

// ---------------------------------------------------------------------------
// Kernel 2: projections. z=0 -> q', z=1 -> k'. grid (8, 16, 2), 256 thr.
// Epilogue: stage fp32 tile row-major in smem (stride 136: 16B-aligned
// float4 reads, scatter-store banks 8g+2tg all distinct), coalesced packed
// hi/lo stores to [m][d2] layout.
// ---------------------------------------------------------------------------
#define EP_ST 136

__global__ void __launch_bounds__(256, 2) proj_mma_kernel(
    const float* __restrict__ bq, const float* __restrict__ bk)
{
    extern __shared__ uint32_t smem[];
    float* smf = (float*)smem;
    const int z = blockIdx.z;
    const int m0 = blockIdx.y * 128, n0 = blockIdx.x * 128;

    const uint32_t* Ah = (z ? g_kh : g_qh) + (size_t)m0 * 512;   // [2048][512]
    const uint32_t* Al = (z ? g_kl : g_ql) + (size_t)m0 * 512;
    const uint32_t* Bh = (z ? g_wkh : g_wqh) + (size_t)n0 * 512; // [1024][512]
    const uint32_t* Bl = (z ? g_wkl : g_wql) + (size_t)n0 * 512;

    float acc[2][8][4];
    #pragma unroll
    for (int i = 0; i < 2; i++)
        #pragma unroll
        for (int j = 0; j < 8; j++)
            #pragma unroll
            for (int r = 0; r < 4; r++) acc[i][j][r] = 0.f;

    gemm_mainloop(Ah, Al, 512, Bh, Bl, 512, NDQ / 32, acc, smem);

    const int warp = threadIdx.x >> 5, lane = threadIdx.x & 31;
    const int warp_m = (warp & 3) * 32, warp_n = (warp >> 2) * 64;
    const int g = lane >> 2, tg = lane & 3;

    __syncthreads();   // smem reuse safe
    // stage acc row-major [m][n], stride 136
    #pragma unroll
    for (int ma = 0; ma < 2; ma++)
        #pragma unroll
        for (int nb = 0; nb < 8; nb++) {
            const int row = warp_m + ma * 16 + g;
            const int col = warp_n + nb * 8 + 2 * tg;
            #pragma unroll
            for (int rr = 0; rr < 4; rr++)
                smf[(row + (rr >> 1) * 8) * EP_ST + col + (rr & 1)] = acc[ma][nb][rr];
        }
    __syncthreads();

    const float* bias = z ? bk : bq;
    uint32_t* Ho = z ? g_pkh : g_pqh;
    uint32_t* Lo = z ? g_pkl : g_pql;

    // bias for this lane's 4 n-values (constant over rows)
    float4 bb = *(const float4*)&bias[n0 + 4 * lane];
    bb.x *= WSCALE; bb.y *= WSCALE; bb.z *= WSCALE; bb.w *= WSCALE;

    #pragma unroll
    for (int i = 0; i < 16; i++) {
        const int row = warp * 16 + i;
        const float4 vv = *(const float4*)&smf[row * EP_ST + 4 * lane];
        uint32_t hw0, lw0, hw1, lw1;
        fp16_split2(vv.x + bb.x, vv.y + bb.y, hw0, lw0);
        fp16_split2(vv.z + bb.z, vv.w + bb.w, hw1, lw1);
        const size_t o = (size_t)(m0 + row) * 512 + (n0 >> 1) + 2 * lane;
        *(uint2*)&Ho[o] = make_uint2(hw0, hw1);
        *(uint2*)&Lo[o] = make_uint2(lw0, lw1);
    }
}

// ---------------------------------------------------------------------------
// Kernel 3: score'[b,v] = q'_v * k'_v^T (K=128, 4096x scaled). grid (8,8,16).
// ---------------------------------------------------------------------------
__global__ void __launch_bounds__(256, 2) score_mma_kernel()
{
    extern __shared__ uint32_t smem[];
    const int z = blockIdx.z;
    const int b = z >> 3, v = z & 7;
    const int m0 = blockIdx.y * 128, n0 = blockIdx.x * 128;

    const uint32_t* Ah = g_pqh + (size_t)(b * 1024 + m0) * 512 + v * 64;
    const uint32_t* Al = g_pql + (size_t)(b * 1024 + m0) * 512 + v * 64;
    const uint32_t* Bh = g_pkh + (size_t)(b * 1024 + n0) * 512 + v * 64;
    const uint32_t* Bl = g_pkl + (size_t)(b * 1024 + n0) * 512 + v * 64;

    float acc[2][8][4];
    #pragma unroll
    for (int i = 0; i < 2; i++)
        #pragma unroll
        for (int j = 0; j < 8; j++)
            #pragma unroll
            for (int r = 0; r < 4; r++) acc[i][j][r] = 0.f;

    gemm_mainloop(Ah, Al, 512, Bh, Bl, 512, NDVP / 32, acc, smem);

    float* C = g_score + ((size_t)z << 20);
    const int warp = threadIdx.x >> 5, lane = threadIdx.x & 31;
    const int warp_m = (warp & 3) * 32, warp_n = (warp >> 2) * 64;
    const int g = lane >> 2, tg = lane & 3;

    #pragma unroll
    for (int ma = 0; ma < 2; ma++)
        #pragma unroll
        for (int nb = 0; nb < 8; nb++) {
            const int row = m0 + warp_m + ma * 16 + g;
            const int col = n0 + warp_n + nb * 8 + 2 * tg;
            *(float2*)&C[(size_t)row * 1024 + col] =
                make_float2(acc[ma][nb][0], acc[ma][nb][1]);
            *(float2*)&C[(size_t)(row + 8) * 1024 + col] =
                make_float2(acc[ma][nb][2], acc[ma][nb][3]);
        }
}

// ---------------------------------------------------------------------------
// Kernel 4: top-8 + softmax per score row (scores are 4096x; softmax rescales).
// ---------------------------------------------------------------------------
__global__ void __launch_bounds__(256) topk_kernel()
{
    const int rid  = blockIdx.x * 8 + (threadIdx.x >> 5);
    const int lane = threadIdx.x & 31;
    const float* row = g_score + (size_t)rid * NL;

    float best[NK];
    int   bidx[NK];
    #pragma unroll
    for (int j = 0; j < NK; j++) { best[j] = -INFINITY; bidx[j] = 0x7fffffff; }

    #pragma unroll 4
    for (int i = 0; i < 32; i++) {
        const int idx = i * 32 + lane;
        const float val = row[idx];
        if (val > best[NK - 1]) {
            best[NK - 1] = val; bidx[NK - 1] = idx;
            #pragma unroll
            for (int j = NK - 1; j > 0; --j) {
                if (best[j] > best[j - 1]) {
                    float tv = best[j]; best[j] = best[j - 1]; best[j - 1] = tv;
                    int   ti = bidx[j]; bidx[j] = bidx[j - 1]; bidx[j - 1] = ti;
                }
            }
        }
    }

    float vals[NK]; int inds[NK];
    #pragma unroll
    for (int r = 0; r < NK; r++) {
        float v0 = best[0]; int i0 = bidx[0];
        #pragma unroll
        for (int off = 16; off > 0; off >>= 1) {
            float ov = __shfl_down_sync(0xffffffffu, v0, off);
            int   oi = __shfl_down_sync(0xffffffffu, i0, off);
            if (ov > v0 || (ov == v0 && oi < i0)) { v0 = ov; i0 = oi; }
        }
        v0 = __shfl_sync(0xffffffffu, v0, 0);
        i0 = __shfl_sync(0xffffffffu, i0, 0);
        vals[r] = v0; inds[r] = i0;
        if (lane == (i0 & 31)) {
            #pragma unroll
            for (int j = 0; j < NK - 1; j++) { best[j] = best[j + 1]; bidx[j] = bidx[j + 1]; }
            best[NK - 1] = -INFINITY; bidx[NK - 1] = 0x7fffffff;
        }
    }

    if (lane == 0) {
        const float m = vals[0];
        float e[NK], sum = 0.f;
        #pragma unroll
        for (int r = 0; r < NK; r++) {
            e[r] = expf((vals[r] - m) * INV_SCORE_SCALE);
            sum += e[r];
        }
        const float inv = 1.f / sum;
        #pragma unroll
        for (int r = 0; r < NK; r++) {
            g_wt[rid * NK + r] = e[r] * inv;
            g_ix[rid * NK + r] = inds[r];
        }
    }
}

// ---------------------------------------------------------------------------
// Kernel 5: windowed gather + weighted sum. grid (1024, 8, 2), 256 threads.
// ---------------------------------------------------------------------------
__global__ void __launch_bounds__(256) out_kernel(
    const float* __restrict__ source, float* __restrict__ out)
{
    const int q = blockIdx.x, v = blockIdx.y, b = blockIdx.z;
    const int tid = threadIdx.x;
    const int rid = (b * NV + v) * NL + q;

    float wloc[NK]; int iloc[NK];
    #pragma unroll
    for (int r = 0; r < NK; r++) {
        wloc[r] = __ldg(&g_wt[rid * NK + r]);
        iloc[r] = __ldg(&g_ix[rid * NK + r]);
    }

    const float4* src4 = (const float4*)(source + b * (NL * NDSRC));
    float4* out4 = (float4*)out + (size_t)rid * (NW * NDSRC / 4);

    #pragma unroll
    for (int e2 = 0; e2 < 2; e2++) {
        const int id = tid + e2 * 256;
        const int w = id >> 7;
        const int f = id & 127;
        float4 acc = make_float4(0.f, 0.f, 0.f, 0.f);
        #pragma unroll
        for (int r = 0; r < NK; r++) {
            const int rr = iloc[r] + w - 1;
            if ((unsigned)rr < (unsigned)NL) {
                const float4 s = __ldg(&src4[rr * (NDSRC / 4) + f]);
                const float wt = wloc[r];
                acc.x += wt * s.x; acc.y += wt * s.y;
                acc.z += wt * s.z; acc.w += wt * s.w;
            }
        }
        out4[id] = acc;
    }
}

// ---------------------------------------------------------------------------
extern "C" void kernel_launch(void* const* d_in, const int* in_sizes, int n_in,
                              void* d_out, int out_size)
{
    const float* query  = (const float*)d_in[0];
    const float* key_t  = (const float*)d_in[1];
    const float* source = (const float*)d_in[2];
    const float* wq     = (const float*)d_in[3];
    const float* bq     = (const float*)d_in[4];
    const float* wk     = (const float*)d_in[5];
    const float* bk     = (const float*)d_in[6];
    float* out = (float*)d_out;

    static int inited = 0;
    if (!inited) {
        cudaFuncSetAttribute(proj_mma_kernel,  cudaFuncAttributeMaxDynamicSharedMemorySize, SMEM_BYTES);
        cudaFuncSetAttribute(score_mma_kernel, cudaFuncAttributeMaxDynamicSharedMemorySize, SMEM_BYTES);
        inited = 1;
    }

    // 1) split inputs into packed fp16 hi/lo row-major (weights scaled by 64)
    split_qk_kernel<<<dim3(4096, 1, 2), 256>>>(query, key_t);
    split_w_kernel<<<dim3(2048, 1, 2), 256>>>(wq, wk);

    // 2) projections (fp16x3 + ldmatrix)
    proj_mma_kernel<<<dim3(8, 16, 2), 256, SMEM_BYTES>>>(bq, bk);

    // 3) score GEMMs (fp16x3 + ldmatrix)
    score_mma_kernel<<<dim3(8, 8, 16), 256, SMEM_BYTES>>>();

    // 4) top-8 + softmax (rescale by 1/4096)
    topk_kernel<<<NROWS / 8, 256>>>();

    // 5) gather + weighted sum
    out_kernel<<<dim3(NL, NV, NB), 256>>>(source, out);
}